// round 11
// baseline (speedup 1.0000x reference)
#include <cuda_runtime.h>
#include <cuda_fp16.h>
#include <cstdint>

#define DEVINL __device__ __forceinline__

namespace {

constexpr int BATCH = 32;
constexpr int LSEQ  = 8192;
constexpr int THREADS = 256;                 // 2 groups x 4 warps
constexpr int GRID = 296;                    // one full wave @ 2 CTAs/SM
constexpr int TILES64_PER_BATCH = 128;       // chunking granularity (64 rows)

// ---- SMEM layout (bytes) ----
constexpr int SM_KSUM = 0;                   // 128 floats
constexpr int SM_XCH  = 512;                 // 2 groups x 64 float2 = 1024
constexpr int SM_PB   = 2048;                // 2 groups x 4096 (P half-buffer, fp16)
constexpr int SM_KH   = 10240;               // 128x128 fp16, XOR-swizzled (rows k-permuted)
constexpr int SM_KL   = SM_KH + 32768;
constexpr int SM_VH   = SM_KL + 32768;
constexpr int SMEM_TOTAL = SM_VH + 32768;    // 108544 -> 2 CTAs/SM

// byte offset of fp16 element (r, c) in a 128x128 tile (256B rows); XOR swizzle
DEVINL uint32_t swz(int r, int c) {
    return (uint32_t)((r << 8) | ((((c >> 3) ^ (r & 7)) << 4) | ((c & 7) << 1)));
}
// same for a 32x64 fp16 tile (128B rows) — the P half-buffer
DEVINL uint32_t swz2(int r, int c) {
    return (uint32_t)((r << 7) | ((((c >> 3) ^ (r & 7)) << 4) | ((c & 7) << 1)));
}

// k-dim permutation (see R8): orig o = 4t+2b+d -> tile pos 8b+2t+d within 16-block
DEVINL int kperm(int r) {
    int o = r & 15;
    return (r & 112) | ((o & 2) << 2) | ((o & 12) >> 1) | (o & 1);
}

DEVINL uint32_t smem_u32(const void* p) {
    uint32_t a;
    asm("{ .reg .u64 t; cvta.to.shared.u64 t, %1; cvt.u32.u64 %0, t; }" : "=r"(a) : "l"(p));
    return a;
}

DEVINL uint32_t packh(__half a, __half b) {
    return (uint32_t)__half_as_ushort(a) | ((uint32_t)__half_as_ushort(b) << 16);
}

DEVINL void split_pack2h(float a, float b, uint32_t& h, uint32_t& l) {
    __half ha = __float2half_rn(a), hb = __float2half_rn(b);
    __half la = __float2half_rn(a - __half2float(ha));
    __half lb = __float2half_rn(b - __half2float(hb));
    h = packh(ha, hb);
    l = packh(la, lb);
}
DEVINL uint32_t pack_hi2(float a, float b) {
    return packh(__float2half_rn(a), __float2half_rn(b));
}
DEVINL uint32_t hmul2u(uint32_t a, uint32_t b) {
    __half2 ha = *reinterpret_cast<__half2*>(&a);
    __half2 hb = *reinterpret_cast<__half2*>(&b);
    __half2 hr = __hmul2(ha, hb);
    return *reinterpret_cast<uint32_t*>(&hr);
}

// ldmatrix x4 address into 256B-row tile
DEVINL uint32_t ldsm_addr(uint32_t tbase, int rbase, int c8base, int lane) {
    int ln = lane & 7, sel = lane >> 3;
    int r  = rbase + ln + ((sel & 1) << 3);
    int c8 = c8base + (sel >> 1);
    return tbase + swz(r, c8 << 3);
}
// ldmatrix x4 address into 128B-row tile (P buffer)
DEVINL uint32_t ldsm_addr2(uint32_t tbase, int rbase, int c8base, int lane) {
    int ln = lane & 7, sel = lane >> 3;
    int r  = rbase + ln + ((sel & 1) << 3);
    int c8 = c8base + (sel >> 1);
    return tbase + swz2(r, c8 << 3);
}

DEVINL void ldsm4(uint32_t a[4], uint32_t addr) {
    asm volatile("ldmatrix.sync.aligned.m8n8.x4.shared.b16 {%0,%1,%2,%3}, [%4];"
                 : "=r"(a[0]), "=r"(a[1]), "=r"(a[2]), "=r"(a[3]) : "r"(addr));
}
DEVINL void ldsm4t(uint32_t a[4], uint32_t addr) {
    asm volatile("ldmatrix.sync.aligned.m8n8.x4.trans.shared.b16 {%0,%1,%2,%3}, [%4];"
                 : "=r"(a[0]), "=r"(a[1]), "=r"(a[2]), "=r"(a[3]) : "r"(addr));
}

DEVINL void mma_fp16(float c[4], const uint32_t a[4], uint32_t b0, uint32_t b1) {
    asm volatile(
        "mma.sync.aligned.m16n8k16.row.col.f32.f16.f16.f32 "
        "{%0,%1,%2,%3}, {%4,%5,%6,%7}, {%8,%9}, {%0,%1,%2,%3};"
        : "+f"(c[0]), "+f"(c[1]), "+f"(c[2]), "+f"(c[3])
        : "r"(a[0]), "r"(a[1]), "r"(a[2]), "r"(a[3]), "r"(b0), "r"(b1));
}

DEVINL void barg(int id) {
    asm volatile("bar.sync %0, 128;" :: "r"(id) : "memory");
}

__global__ void __launch_bounds__(THREADS, 2)
axial_attn_kernel(const float* __restrict__ q, const float* __restrict__ k,
                  const float* __restrict__ v, float* __restrict__ out) {
    extern __shared__ char smem[];
    const uint32_t sb = smem_u32(smem);
    const int tid  = threadIdx.x;
    const int lane = tid & 31, w = tid >> 5;
    const int grp  = w >> 2;       // independent tile-stream group
    const int wr   = (w >> 1) & 1; // row group within 32-row tile
    const int sgrp = w & 1;        // S-half (GEMM1) / d-half (GEMM2)
    const int g = lane >> 2, t = lane & 3;

    // ---- CTA -> (batch, 64-row tile chunk). 296 = 8*10 + 24*9 ----
    int bx = blockIdx.x;
    int batch, cidx, ncta;
    if (bx < 80) { batch = bx / 10; cidx = bx - batch * 10; ncta = 10; }
    else { int r = bx - 80; int bb = r / 9; batch = 8 + bb; cidx = r - bb * 9; ncta = 9; }
    const int base = TILES64_PER_BATCH / ncta, rem = TILES64_PER_BATCH - base * ncta;
    int tstart, tcnt;
    if (cidx < rem) { tcnt = base + 1; tstart = cidx * tcnt; }
    else            { tcnt = base;     tstart = rem * (base + 1) + (cidx - rem) * base; }

    float*  ksum = reinterpret_cast<float*>(smem + SM_KSUM);
    float2* xch  = reinterpret_cast<float2*>(smem + SM_XCH) + grp * 64;
    const int pbo = SM_PB + grp * 4096;
    const uint32_t pb = sb + pbo;

    const float* kb = k + (size_t)batch * (128 * 128);
    const float* vb = v + (size_t)batch * (128 * 128);

    // ======== one-time fill: K (hi/lo, k-permuted rows, + row sums), V (hi) ========
    {
        const float4* kb4 = reinterpret_cast<const float4*>(kb);
        #pragma unroll 4
        for (int it = 0; it < 16; it++) {
            int e4  = it * THREADS + tid;          // warp covers exactly one row
            int row = e4 >> 5;
            int col = (e4 & 31) << 2;
            float4 tk = kb4[e4];
            uint32_t h01, l01, h23, l23;
            split_pack2h(tk.x, tk.y, h01, l01);
            split_pack2h(tk.z, tk.w, h23, l23);
            uint32_t off = swz(kperm(row), col);
            *reinterpret_cast<uint2*>(smem + SM_KH + off) = make_uint2(h01, h23);
            *reinterpret_cast<uint2*>(smem + SM_KL + off) = make_uint2(l01, l23);
            float s = (tk.x + tk.y) + (tk.z + tk.w);
            s += __shfl_xor_sync(0xffffffffu, s, 16);
            s += __shfl_xor_sync(0xffffffffu, s, 8);
            s += __shfl_xor_sync(0xffffffffu, s, 4);
            s += __shfl_xor_sync(0xffffffffu, s, 2);
            s += __shfl_xor_sync(0xffffffffu, s, 1);
            if (lane == 0) ksum[row] = s;
        }
        const float4* vb4 = reinterpret_cast<const float4*>(vb);
        #pragma unroll 4
        for (int it = 0; it < 16; it++) {
            int e4  = it * THREADS + tid;
            int row = e4 >> 5;
            int col = (e4 & 31) << 2;
            float4 tv = vb4[e4];
            uint32_t off = swz(row, col);
            *reinterpret_cast<uint2*>(smem + SM_VH + off) =
                make_uint2(pack_hi2(tv.x, tv.y), pack_hi2(tv.z, tv.w));
        }
    }
    __syncthreads();

    // ksum for this warp's S-half, hoisted to registers (tile-invariant)
    float ksA[8], ksB[8];
    #pragma unroll
    for (int jt = 0; jt < 8; jt++) {
        float2 ks2 = *reinterpret_cast<const float2*>(ksum + 64 * sgrp + 8 * jt + 2 * t);
        ksA[jt] = ks2.x; ksB[jt] = ks2.y;
    }

    const int barid = 1 + grp;
    const float* qwbase = q + (size_t)batch * LSEQ * 128 + (16 * wr + g) * 128 + 4 * t;

    // preload row-g half of Q for first tile
    float4 qf0[8], qf1[8];
    {
        const float* p0 = qwbase + (size_t)((2 * tstart + grp) * 32) * 128;
        #pragma unroll
        for (int kk = 0; kk < 8; kk++)
            qf0[kk] = *reinterpret_cast<const float4*>(p0 + 16 * kk);
    }

    // ======== per-group tile loop (32-row tiles) ========
    for (int ti = 0; ti < tcnt; ti++) {
        const int l0 = (2 * (tstart + ti) + grp) * 32;

        // row g+8 half loads now; qf0 was prefetched last iteration
        {
            const float* p1 = qwbase + ((size_t)l0 + 8) * 128;
            #pragma unroll
            for (int kk = 0; kk < 8; kk++)
                qf1[kk] = *reinterpret_cast<const float4*>(p1 + 16 * kk);
        }

        // ---- GEMM1 (kk-outer, transient A frags): S = Qh*Kh + Qh*Kl + Ql*Kh ----
        // qsum accumulated inline so MMAs can start before all Q arrives
        float C1[8][4];
        #pragma unroll
        for (int jt = 0; jt < 8; jt++)
            #pragma unroll
            for (int i = 0; i < 4; i++) C1[jt][i] = 0.f;

        float qs_lo = 0.f, qs_hi = 0.f;
        #pragma unroll
        for (int kk = 0; kk < 8; kk++) {
            qs_lo += (qf0[kk].x + qf0[kk].y) + (qf0[kk].z + qf0[kk].w);
            qs_hi += (qf1[kk].x + qf1[kk].y) + (qf1[kk].z + qf1[kk].w);
            uint32_t A_h[4], A_l[4];
            split_pack2h(qf0[kk].x, qf0[kk].y, A_h[0], A_l[0]);
            split_pack2h(qf1[kk].x, qf1[kk].y, A_h[1], A_l[1]);
            split_pack2h(qf0[kk].z, qf0[kk].w, A_h[2], A_l[2]);
            split_pack2h(qf1[kk].z, qf1[kk].w, A_h[3], A_l[3]);
            #pragma unroll
            for (int jp = 0; jp < 4; jp++) {
                const int c8 = 2 * (4 * sgrp + jp);
                uint32_t bh[4], bl[4];
                ldsm4t(bh, ldsm_addr(sb + SM_KH, 16 * kk, c8, lane));
                ldsm4t(bl, ldsm_addr(sb + SM_KL, 16 * kk, c8, lane));
                mma_fp16(C1[2 * jp],     A_h, bh[0], bh[1]);
                mma_fp16(C1[2 * jp + 1], A_h, bh[2], bh[3]);
                mma_fp16(C1[2 * jp],     A_h, bl[0], bl[1]);
                mma_fp16(C1[2 * jp + 1], A_h, bl[2], bl[3]);
                mma_fp16(C1[2 * jp],     A_l, bh[0], bh[1]);
                mma_fp16(C1[2 * jp + 1], A_l, bh[2], bh[3]);
            }
        }
        qs_lo += __shfl_xor_sync(0xffffffffu, qs_lo, 1);
        qs_lo += __shfl_xor_sync(0xffffffffu, qs_lo, 2);
        qs_hi += __shfl_xor_sync(0xffffffffu, qs_hi, 1);
        qs_hi += __shfl_xor_sync(0xffffffffu, qs_hi, 2);

        // ---- exact rank-1 term ----
        #pragma unroll
        for (int jt = 0; jt < 8; jt++) {
            C1[jt][0] += qs_lo * ksA[jt];
            C1[jt][1] += qs_lo * ksB[jt];
            C1[jt][2] += qs_hi * ksA[jt];
            C1[jt][3] += qs_hi * ksB[jt];
        }

        // ---- local softmax stats + exp (unscaled) ----
        float mlo = -3.4e38f, mhi = -3.4e38f;
        #pragma unroll
        for (int jt = 0; jt < 8; jt++) {
            mlo = fmaxf(mlo, fmaxf(C1[jt][0], C1[jt][1]));
            mhi = fmaxf(mhi, fmaxf(C1[jt][2], C1[jt][3]));
        }
        mlo = fmaxf(mlo, __shfl_xor_sync(0xffffffffu, mlo, 1));
        mlo = fmaxf(mlo, __shfl_xor_sync(0xffffffffu, mlo, 2));
        mhi = fmaxf(mhi, __shfl_xor_sync(0xffffffffu, mhi, 1));
        mhi = fmaxf(mhi, __shfl_xor_sync(0xffffffffu, mhi, 2));

        float slo = 0.f, shi = 0.f;
        #pragma unroll
        for (int jt = 0; jt < 8; jt++) {
            C1[jt][0] = __expf(C1[jt][0] - mlo);
            C1[jt][1] = __expf(C1[jt][1] - mlo);
            C1[jt][2] = __expf(C1[jt][2] - mhi);
            C1[jt][3] = __expf(C1[jt][3] - mhi);
            slo += C1[jt][0] + C1[jt][1];
            shi += C1[jt][2] + C1[jt][3];
        }
        slo += __shfl_xor_sync(0xffffffffu, slo, 1);
        slo += __shfl_xor_sync(0xffffffffu, slo, 2);
        shi += __shfl_xor_sync(0xffffffffu, shi, 1);
        shi += __shfl_xor_sync(0xffffffffu, shi, 2);

        if (t == 0) {
            xch[sgrp * 32 + 16 * wr + g]     = make_float2(mlo, slo);
            xch[sgrp * 32 + 16 * wr + g + 8] = make_float2(mhi, shi);
        }
        // round 0: S-half 0 warps write their UNSCALED P immediately
        if (sgrp == 0) {
            #pragma unroll
            for (int jt = 0; jt < 8; jt++) {
                *reinterpret_cast<uint32_t*>(smem + pbo + swz2(16 * wr + g,     8 * jt + 2 * t)) =
                    pack_hi2(C1[jt][0], C1[jt][1]);
                *reinterpret_cast<uint32_t*>(smem + pbo + swz2(16 * wr + g + 8, 8 * jt + 2 * t)) =
                    pack_hi2(C1[jt][2], C1[jt][3]);
            }
        }
        barg(barid);   // publishes stats + P half 0

        // ---- global scales; fold rescale AND 1/sum into per-row fp16 factors ----
        float2 o_lo = xch[(1 - sgrp) * 32 + 16 * wr + g];
        float2 o_hi = xch[(1 - sgrp) * 32 + 16 * wr + g + 8];
        const float Mlo = fmaxf(mlo, o_lo.x);
        const float Mhi = fmaxf(mhi, o_hi.x);
        const float sc_lo = __expf(mlo - Mlo),   sc_hi = __expf(mhi - Mhi);
        const float sp_lo = __expf(o_lo.x - Mlo), sp_hi = __expf(o_hi.x - Mhi);
        const float inv_lo = 1.0f / (slo * sc_lo + o_lo.y * sp_lo);
        const float inv_hi = 1.0f / (shi * sc_hi + o_hi.y * sp_hi);
        const float f0l = ((sgrp == 0) ? sc_lo : sp_lo) * inv_lo;
        const float f0h = ((sgrp == 0) ? sc_hi : sp_hi) * inv_hi;
        const float f1l = ((sgrp == 1) ? sc_lo : sp_lo) * inv_lo;
        const float f1h = ((sgrp == 1) ? sc_hi : sp_hi) * inv_hi;
        const uint32_t F0l = pack_hi2(f0l, f0l), F0h = pack_hi2(f0h, f0h);
        const uint32_t F1l = pack_hi2(f1l, f1l), F1h = pack_hi2(f1h, f1h);

        // ---- ldsm P half 0, scale in fp16 ----
        uint32_t A2[8][4];
        #pragma unroll
        for (int kkq = 0; kkq < 4; kkq++) {
            ldsm4(A2[kkq], ldsm_addr2(pb, 16 * wr, 2 * kkq, lane));
            A2[kkq][0] = hmul2u(A2[kkq][0], F0l);
            A2[kkq][1] = hmul2u(A2[kkq][1], F0h);
            A2[kkq][2] = hmul2u(A2[kkq][2], F0l);
            A2[kkq][3] = hmul2u(A2[kkq][3], F0h);
        }
        barg(barid);   // half-0 reads done; buffer free

        // round 1: S-half 1 warps write their unscaled P
        if (sgrp == 1) {
            #pragma unroll
            for (int jt = 0; jt < 8; jt++) {
                *reinterpret_cast<uint32_t*>(smem + pbo + swz2(16 * wr + g,     8 * jt + 2 * t)) =
                    pack_hi2(C1[jt][0], C1[jt][1]);
                *reinterpret_cast<uint32_t*>(smem + pbo + swz2(16 * wr + g + 8, 8 * jt + 2 * t)) =
                    pack_hi2(C1[jt][2], C1[jt][3]);
            }
        }

        // ---- GEMM2a (kk 0..3) overlaps the round-1 write/barrier ----
        float C2[8][4];
        #pragma unroll
        for (int n = 0; n < 8; n++)
            #pragma unroll
            for (int i = 0; i < 4; i++) C2[n][i] = 0.f;

        #pragma unroll
        for (int kk = 0; kk < 4; kk++) {
            #pragma unroll
            for (int jp = 0; jp < 4; jp++) {
                const int c8 = 8 * sgrp + 2 * jp;     // this warp's d-half
                uint32_t bh[4];
                ldsm4t(bh, ldsm_addr(sb + SM_VH, 16 * kk, c8, lane));
                mma_fp16(C2[2 * jp],     A2[kk], bh[0], bh[1]);
                mma_fp16(C2[2 * jp + 1], A2[kk], bh[2], bh[3]);
            }
        }
        barg(barid);   // half-1 written

        #pragma unroll
        for (int kkq = 0; kkq < 4; kkq++) {
            ldsm4(A2[4 + kkq], ldsm_addr2(pb, 16 * wr, 2 * kkq, lane));
            A2[4 + kkq][0] = hmul2u(A2[4 + kkq][0], F1l);
            A2[4 + kkq][1] = hmul2u(A2[4 + kkq][1], F1h);
            A2[4 + kkq][2] = hmul2u(A2[4 + kkq][2], F1l);
            A2[4 + kkq][3] = hmul2u(A2[4 + kkq][3], F1h);
        }

        // ---- prefetch next tile's row-g Q half (hidden under GEMM2b+store) ----
        if (ti + 1 < tcnt) {
            const float* p0 = qwbase + ((size_t)l0 + 64) * 128;
            #pragma unroll
            for (int kk = 0; kk < 8; kk++)
                qf0[kk] = *reinterpret_cast<const float4*>(p0 + 16 * kk);
        }
        barg(barid);   // half-1 reads done; buffer free for next tile

        // ---- GEMM2b (kk 4..7) ----
        #pragma unroll
        for (int kk = 4; kk < 8; kk++) {
            #pragma unroll
            for (int jp = 0; jp < 4; jp++) {
                const int c8 = 8 * sgrp + 2 * jp;
                uint32_t bh[4];
                ldsm4t(bh, ldsm_addr(sb + SM_VH, 16 * kk, c8, lane));
                mma_fp16(C2[2 * jp],     A2[kk], bh[0], bh[1]);
                mma_fp16(C2[2 * jp + 1], A2[kk], bh[2], bh[3]);
            }
        }

        // ---- store (normalization already folded into A-fragments) ----
        float* og = out + ((size_t)batch * LSEQ + l0 + 16 * wr) * 128 + 64 * sgrp;
        #pragma unroll
        for (int n = 0; n < 8; n++) {
            const int col = 8 * n + 2 * t;
            *reinterpret_cast<float2*>(og + (size_t)g * 128 + col) =
                make_float2(C2[n][0], C2[n][1]);
            *reinterpret_cast<float2*>(og + (size_t)(g + 8) * 128 + col) =
                make_float2(C2[n][2], C2[n][3]);
        }
    }
}

} // anonymous namespace

extern "C" void kernel_launch(void* const* d_in, const int* in_sizes, int n_in,
                              void* d_out, int out_size) {
    const float* q = (const float*)d_in[0];
    const float* k = (const float*)d_in[1];
    const float* v = (const float*)d_in[2];
    float* out = (float*)d_out;

    cudaFuncSetAttribute(axial_attn_kernel,
                         cudaFuncAttributeMaxDynamicSharedMemorySize, SMEM_TOTAL);
    axial_attn_kernel<<<GRID, THREADS, SMEM_TOTAL>>>(q, k, v, out);
}

// round 12
// speedup vs baseline: 1.0748x; 1.0748x over previous
#include <cuda_runtime.h>
#include <cuda_fp16.h>
#include <cstdint>

#define DEVINL __device__ __forceinline__

namespace {

constexpr int BATCH = 32;
constexpr int LSEQ  = 8192;
constexpr int THREADS = 256;                 // 2 groups x 4 warps
constexpr int GRID = 296;                    // one full wave @ 2 CTAs/SM
constexpr int TILES64_PER_BATCH = 128;       // chunking granularity (64 rows)

// ---- SMEM layout (bytes) ----
constexpr int SM_KSUM = 0;                   // 128 floats
constexpr int SM_XCH  = 512;                 // 2 groups x 64 float2 = 1024
constexpr int SM_PB   = 2048;                // 2 groups x 4096 (P half-buffer, fp16)
constexpr int SM_KH   = 10240;               // 128x128 fp16, XOR-swizzled (rows k-permuted)
constexpr int SM_KL   = SM_KH + 32768;
constexpr int SM_VH   = SM_KL + 32768;
constexpr int SMEM_TOTAL = SM_VH + 32768;    // 108544 -> 2 CTAs/SM

// byte offset of fp16 element (r, c) in a 128x128 tile (256B rows); XOR swizzle
DEVINL uint32_t swz(int r, int c) {
    return (uint32_t)((r << 8) | ((((c >> 3) ^ (r & 7)) << 4) | ((c & 7) << 1)));
}
// same for a 32x64 fp16 tile (128B rows) — the P half-buffer
DEVINL uint32_t swz2(int r, int c) {
    return (uint32_t)((r << 7) | ((((c >> 3) ^ (r & 7)) << 4) | ((c & 7) << 1)));
}

// k-dim permutation (see R8): orig o = 4t+2b+d -> tile pos 8b+2t+d within 16-block
DEVINL int kperm(int r) {
    int o = r & 15;
    return (r & 112) | ((o & 2) << 2) | ((o & 12) >> 1) | (o & 1);
}

DEVINL uint32_t smem_u32(const void* p) {
    uint32_t a;
    asm("{ .reg .u64 t; cvta.to.shared.u64 t, %1; cvt.u32.u64 %0, t; }" : "=r"(a) : "l"(p));
    return a;
}

DEVINL uint32_t packh(__half a, __half b) {
    return (uint32_t)__half_as_ushort(a) | ((uint32_t)__half_as_ushort(b) << 16);
}

DEVINL void split_pack2h(float a, float b, uint32_t& h, uint32_t& l) {
    __half ha = __float2half_rn(a), hb = __float2half_rn(b);
    __half la = __float2half_rn(a - __half2float(ha));
    __half lb = __float2half_rn(b - __half2float(hb));
    h = packh(ha, hb);
    l = packh(la, lb);
}
DEVINL uint32_t pack_hi2(float a, float b) {
    return packh(__float2half_rn(a), __float2half_rn(b));
}
DEVINL uint32_t hmul2u(uint32_t a, uint32_t b) {
    __half2 ha = *reinterpret_cast<__half2*>(&a);
    __half2 hb = *reinterpret_cast<__half2*>(&b);
    __half2 hr = __hmul2(ha, hb);
    return *reinterpret_cast<uint32_t*>(&hr);
}

// ldmatrix x4 address into 256B-row tile
DEVINL uint32_t ldsm_addr(uint32_t tbase, int rbase, int c8base, int lane) {
    int ln = lane & 7, sel = lane >> 3;
    int r  = rbase + ln + ((sel & 1) << 3);
    int c8 = c8base + (sel >> 1);
    return tbase + swz(r, c8 << 3);
}
// ldmatrix x4 address into 128B-row tile (P buffer)
DEVINL uint32_t ldsm_addr2(uint32_t tbase, int rbase, int c8base, int lane) {
    int ln = lane & 7, sel = lane >> 3;
    int r  = rbase + ln + ((sel & 1) << 3);
    int c8 = c8base + (sel >> 1);
    return tbase + swz2(r, c8 << 3);
}

DEVINL void ldsm4(uint32_t a[4], uint32_t addr) {
    asm volatile("ldmatrix.sync.aligned.m8n8.x4.shared.b16 {%0,%1,%2,%3}, [%4];"
                 : "=r"(a[0]), "=r"(a[1]), "=r"(a[2]), "=r"(a[3]) : "r"(addr));
}
DEVINL void ldsm4t(uint32_t a[4], uint32_t addr) {
    asm volatile("ldmatrix.sync.aligned.m8n8.x4.trans.shared.b16 {%0,%1,%2,%3}, [%4];"
                 : "=r"(a[0]), "=r"(a[1]), "=r"(a[2]), "=r"(a[3]) : "r"(addr));
}

DEVINL void mma_fp16(float c[4], const uint32_t a[4], uint32_t b0, uint32_t b1) {
    asm volatile(
        "mma.sync.aligned.m16n8k16.row.col.f32.f16.f16.f32 "
        "{%0,%1,%2,%3}, {%4,%5,%6,%7}, {%8,%9}, {%0,%1,%2,%3};"
        : "+f"(c[0]), "+f"(c[1]), "+f"(c[2]), "+f"(c[3])
        : "r"(a[0]), "r"(a[1]), "r"(a[2]), "r"(a[3]), "r"(b0), "r"(b1));
}

DEVINL void barg(int id) {
    asm volatile("bar.sync %0, 128;" :: "r"(id) : "memory");
}

__global__ void __launch_bounds__(THREADS, 2)
axial_attn_kernel(const float* __restrict__ q, const float* __restrict__ k,
                  const float* __restrict__ v, float* __restrict__ out) {
    extern __shared__ char smem[];
    const uint32_t sb = smem_u32(smem);
    const int tid  = threadIdx.x;
    const int lane = tid & 31, w = tid >> 5;
    const int grp  = w >> 2;       // independent tile-stream group
    const int wr   = (w >> 1) & 1; // row group within 32-row tile
    const int sgrp = w & 1;        // S-half (GEMM1) / d-half (GEMM2)
    const int g = lane >> 2, t = lane & 3;

    // ---- CTA -> (batch, 64-row tile chunk). 296 = 8*10 + 24*9 ----
    int bx = blockIdx.x;
    int batch, cidx, ncta;
    if (bx < 80) { batch = bx / 10; cidx = bx - batch * 10; ncta = 10; }
    else { int r = bx - 80; int bb = r / 9; batch = 8 + bb; cidx = r - bb * 9; ncta = 9; }
    const int base = TILES64_PER_BATCH / ncta, rem = TILES64_PER_BATCH - base * ncta;
    int tstart, tcnt;
    if (cidx < rem) { tcnt = base + 1; tstart = cidx * tcnt; }
    else            { tcnt = base;     tstart = rem * (base + 1) + (cidx - rem) * base; }

    float*  ksum = reinterpret_cast<float*>(smem + SM_KSUM);
    float2* xch  = reinterpret_cast<float2*>(smem + SM_XCH) + grp * 64;
    const int pbo = SM_PB + grp * 4096;
    const uint32_t pb = sb + pbo;

    const float* kb = k + (size_t)batch * (128 * 128);
    const float* vb = v + (size_t)batch * (128 * 128);

    // ======== one-time fill: K (hi/lo, k-permuted rows, + row sums), V (hi) ========
    {
        const float4* kb4 = reinterpret_cast<const float4*>(kb);
        #pragma unroll 4
        for (int it = 0; it < 16; it++) {
            int e4  = it * THREADS + tid;          // warp covers exactly one row
            int row = e4 >> 5;
            int col = (e4 & 31) << 2;
            float4 tk = kb4[e4];
            uint32_t h01, l01, h23, l23;
            split_pack2h(tk.x, tk.y, h01, l01);
            split_pack2h(tk.z, tk.w, h23, l23);
            uint32_t off = swz(kperm(row), col);
            *reinterpret_cast<uint2*>(smem + SM_KH + off) = make_uint2(h01, h23);
            *reinterpret_cast<uint2*>(smem + SM_KL + off) = make_uint2(l01, l23);
            float s = (tk.x + tk.y) + (tk.z + tk.w);
            s += __shfl_xor_sync(0xffffffffu, s, 16);
            s += __shfl_xor_sync(0xffffffffu, s, 8);
            s += __shfl_xor_sync(0xffffffffu, s, 4);
            s += __shfl_xor_sync(0xffffffffu, s, 2);
            s += __shfl_xor_sync(0xffffffffu, s, 1);
            if (lane == 0) ksum[row] = s;
        }
        const float4* vb4 = reinterpret_cast<const float4*>(vb);
        #pragma unroll 4
        for (int it = 0; it < 16; it++) {
            int e4  = it * THREADS + tid;
            int row = e4 >> 5;
            int col = (e4 & 31) << 2;
            float4 tv = vb4[e4];
            uint32_t off = swz(row, col);
            *reinterpret_cast<uint2*>(smem + SM_VH + off) =
                make_uint2(pack_hi2(tv.x, tv.y), pack_hi2(tv.z, tv.w));
        }
    }
    __syncthreads();

    // ksum for this warp's S-half, hoisted to registers (tile-invariant)
    float ksA[8], ksB[8];
    #pragma unroll
    for (int jt = 0; jt < 8; jt++) {
        float2 ks2 = *reinterpret_cast<const float2*>(ksum + 64 * sgrp + 8 * jt + 2 * t);
        ksA[jt] = ks2.x; ksB[jt] = ks2.y;
    }

    const int barid = 1 + grp;

    // ======== per-group tile loop (32-row tiles) ========
    for (int ti = 0; ti < tcnt; ti++) {
        const int l0 = (2 * (tstart + ti) + grp) * 32;

        // ---- Q: one float4 per (rowhalf, kk) IS the A-fragment (k-permuted) ----
        const float* qr0 = q + ((size_t)batch * LSEQ + l0 + 16 * wr + g) * 128 + 4 * t;
        const float* qr1 = qr0 + 8 * 128;
        float4 qf0[8], qf1[8];
        #pragma unroll
        for (int kk = 0; kk < 8; kk++) {
            qf0[kk] = *reinterpret_cast<const float4*>(qr0 + 16 * kk);
            qf1[kk] = *reinterpret_cast<const float4*>(qr1 + 16 * kk);
        }

        // ---- qsum (exact fp32, quad-reduced) ----
        float qs_lo = 0.f, qs_hi = 0.f;
        #pragma unroll
        for (int kk = 0; kk < 8; kk++) {
            qs_lo += (qf0[kk].x + qf0[kk].y) + (qf0[kk].z + qf0[kk].w);
            qs_hi += (qf1[kk].x + qf1[kk].y) + (qf1[kk].z + qf1[kk].w);
        }
        qs_lo += __shfl_xor_sync(0xffffffffu, qs_lo, 1);
        qs_lo += __shfl_xor_sync(0xffffffffu, qs_lo, 2);
        qs_hi += __shfl_xor_sync(0xffffffffu, qs_hi, 1);
        qs_hi += __shfl_xor_sync(0xffffffffu, qs_hi, 2);

        // ---- GEMM1 (kk-outer, transient A frags): S = Qh*Kh + Qh*Kl + Ql*Kh ----
        float C1[8][4];
        #pragma unroll
        for (int jt = 0; jt < 8; jt++)
            #pragma unroll
            for (int i = 0; i < 4; i++) C1[jt][i] = 0.f;

        #pragma unroll
        for (int kk = 0; kk < 8; kk++) {
            uint32_t A_h[4], A_l[4];
            split_pack2h(qf0[kk].x, qf0[kk].y, A_h[0], A_l[0]);
            split_pack2h(qf1[kk].x, qf1[kk].y, A_h[1], A_l[1]);
            split_pack2h(qf0[kk].z, qf0[kk].w, A_h[2], A_l[2]);
            split_pack2h(qf1[kk].z, qf1[kk].w, A_h[3], A_l[3]);
            #pragma unroll
            for (int jp = 0; jp < 4; jp++) {
                const int c8 = 2 * (4 * sgrp + jp);
                uint32_t bh[4], bl[4];
                ldsm4t(bh, ldsm_addr(sb + SM_KH, 16 * kk, c8, lane));
                ldsm4t(bl, ldsm_addr(sb + SM_KL, 16 * kk, c8, lane));
                mma_fp16(C1[2 * jp],     A_h, bh[0], bh[1]);
                mma_fp16(C1[2 * jp + 1], A_h, bh[2], bh[3]);
                mma_fp16(C1[2 * jp],     A_h, bl[0], bl[1]);
                mma_fp16(C1[2 * jp + 1], A_h, bl[2], bl[3]);
                mma_fp16(C1[2 * jp],     A_l, bh[0], bh[1]);
                mma_fp16(C1[2 * jp + 1], A_l, bh[2], bh[3]);
            }
        }

        // ---- exact rank-1 term ----
        #pragma unroll
        for (int jt = 0; jt < 8; jt++) {
            C1[jt][0] += qs_lo * ksA[jt];
            C1[jt][1] += qs_lo * ksB[jt];
            C1[jt][2] += qs_hi * ksA[jt];
            C1[jt][3] += qs_hi * ksB[jt];
        }

        // ---- local softmax stats + exp (unscaled) ----
        float mlo = -3.4e38f, mhi = -3.4e38f;
        #pragma unroll
        for (int jt = 0; jt < 8; jt++) {
            mlo = fmaxf(mlo, fmaxf(C1[jt][0], C1[jt][1]));
            mhi = fmaxf(mhi, fmaxf(C1[jt][2], C1[jt][3]));
        }
        mlo = fmaxf(mlo, __shfl_xor_sync(0xffffffffu, mlo, 1));
        mlo = fmaxf(mlo, __shfl_xor_sync(0xffffffffu, mlo, 2));
        mhi = fmaxf(mhi, __shfl_xor_sync(0xffffffffu, mhi, 1));
        mhi = fmaxf(mhi, __shfl_xor_sync(0xffffffffu, mhi, 2));

        float slo = 0.f, shi = 0.f;
        #pragma unroll
        for (int jt = 0; jt < 8; jt++) {
            C1[jt][0] = __expf(C1[jt][0] - mlo);
            C1[jt][1] = __expf(C1[jt][1] - mlo);
            C1[jt][2] = __expf(C1[jt][2] - mhi);
            C1[jt][3] = __expf(C1[jt][3] - mhi);
            slo += C1[jt][0] + C1[jt][1];
            shi += C1[jt][2] + C1[jt][3];
        }
        slo += __shfl_xor_sync(0xffffffffu, slo, 1);
        slo += __shfl_xor_sync(0xffffffffu, slo, 2);
        shi += __shfl_xor_sync(0xffffffffu, shi, 1);
        shi += __shfl_xor_sync(0xffffffffu, shi, 2);

        // publish stats; half-0 warps write UNSCALED P immediately (no dependency
        // on partner stats) — one barrier covers both
        if (t == 0) {
            xch[sgrp * 32 + 16 * wr + g]     = make_float2(mlo, slo);
            xch[sgrp * 32 + 16 * wr + g + 8] = make_float2(mhi, shi);
        }
        if (sgrp == 0) {
            #pragma unroll
            for (int jt = 0; jt < 8; jt++) {
                *reinterpret_cast<uint32_t*>(smem + pbo + swz2(16 * wr + g,     8 * jt + 2 * t)) =
                    pack_hi2(C1[jt][0], C1[jt][1]);
                *reinterpret_cast<uint32_t*>(smem + pbo + swz2(16 * wr + g + 8, 8 * jt + 2 * t)) =
                    pack_hi2(C1[jt][2], C1[jt][3]);
            }
        }
        barg(barid);   // stats + P half-0 visible

        // ---- global scales; fold rescale AND 1/sum into per-row fp16 factors ----
        float2 o_lo = xch[(1 - sgrp) * 32 + 16 * wr + g];
        float2 o_hi = xch[(1 - sgrp) * 32 + 16 * wr + g + 8];
        const float Mlo = fmaxf(mlo, o_lo.x);
        const float Mhi = fmaxf(mhi, o_hi.x);
        const float sc_lo = __expf(mlo - Mlo),    sc_hi = __expf(mhi - Mhi);
        const float sp_lo = __expf(o_lo.x - Mlo), sp_hi = __expf(o_hi.x - Mhi);
        const float inv_lo = 1.0f / (slo * sc_lo + o_lo.y * sp_lo);
        const float inv_hi = 1.0f / (shi * sc_hi + o_hi.y * sp_hi);
        const float f0l = ((sgrp == 0) ? sc_lo : sp_lo) * inv_lo;
        const float f0h = ((sgrp == 0) ? sc_hi : sp_hi) * inv_hi;
        const float f1l = ((sgrp == 1) ? sc_lo : sp_lo) * inv_lo;
        const float f1h = ((sgrp == 1) ? sc_hi : sp_hi) * inv_hi;
        const uint32_t F0l = pack_hi2(f0l, f0l), F0h = pack_hi2(f0h, f0h);
        const uint32_t F1l = pack_hi2(f1l, f1l), F1h = pack_hi2(f1h, f1h);

        // ---- ldsm P half-0, scale in fp16 ----
        uint32_t A2[8][4];
        #pragma unroll
        for (int kkq = 0; kkq < 4; kkq++) {
            ldsm4(A2[kkq], ldsm_addr2(pb, 16 * wr, 2 * kkq, lane));
            A2[kkq][0] = hmul2u(A2[kkq][0], F0l);
            A2[kkq][1] = hmul2u(A2[kkq][1], F0h);
            A2[kkq][2] = hmul2u(A2[kkq][2], F0l);
            A2[kkq][3] = hmul2u(A2[kkq][3], F0h);
        }
        barg(barid);   // half-0 reads done; buffer free

        // half-1 warps write their unscaled P
        if (sgrp == 1) {
            #pragma unroll
            for (int jt = 0; jt < 8; jt++) {
                *reinterpret_cast<uint32_t*>(smem + pbo + swz2(16 * wr + g,     8 * jt + 2 * t)) =
                    pack_hi2(C1[jt][0], C1[jt][1]);
                *reinterpret_cast<uint32_t*>(smem + pbo + swz2(16 * wr + g + 8, 8 * jt + 2 * t)) =
                    pack_hi2(C1[jt][2], C1[jt][3]);
            }
        }

        // ---- GEMM2a (kk 0..3) overlaps the half-1 write/barrier ----
        float C2[8][4];
        #pragma unroll
        for (int n = 0; n < 8; n++)
            #pragma unroll
            for (int i = 0; i < 4; i++) C2[n][i] = 0.f;

        #pragma unroll
        for (int kk = 0; kk < 4; kk++) {
            #pragma unroll
            for (int jp = 0; jp < 4; jp++) {
                const int c8 = 8 * sgrp + 2 * jp;     // this warp's d-half
                uint32_t bh[4];
                ldsm4t(bh, ldsm_addr(sb + SM_VH, 16 * kk, c8, lane));
                mma_fp16(C2[2 * jp],     A2[kk], bh[0], bh[1]);
                mma_fp16(C2[2 * jp + 1], A2[kk], bh[2], bh[3]);
            }
        }
        barg(barid);   // half-1 written

        // ---- ldsm P half-1, scale in fp16 ----
        #pragma unroll
        for (int kkq = 0; kkq < 4; kkq++) {
            ldsm4(A2[4 + kkq], ldsm_addr2(pb, 16 * wr, 2 * kkq, lane));
            A2[4 + kkq][0] = hmul2u(A2[4 + kkq][0], F1l);
            A2[4 + kkq][1] = hmul2u(A2[4 + kkq][1], F1h);
            A2[4 + kkq][2] = hmul2u(A2[4 + kkq][2], F1l);
            A2[4 + kkq][3] = hmul2u(A2[4 + kkq][3], F1h);
        }
        barg(barid);   // half-1 reads done; buffer free for next tile

        // ---- GEMM2b (kk 4..7) ----
        #pragma unroll
        for (int kk = 4; kk < 8; kk++) {
            #pragma unroll
            for (int jp = 0; jp < 4; jp++) {
                const int c8 = 8 * sgrp + 2 * jp;
                uint32_t bh[4];
                ldsm4t(bh, ldsm_addr(sb + SM_VH, 16 * kk, c8, lane));
                mma_fp16(C2[2 * jp],     A2[kk], bh[0], bh[1]);
                mma_fp16(C2[2 * jp + 1], A2[kk], bh[2], bh[3]);
            }
        }

        // ---- store (normalization already folded into A-fragments) ----
        float* og = out + ((size_t)batch * LSEQ + l0 + 16 * wr) * 128 + 64 * sgrp;
        #pragma unroll
        for (int n = 0; n < 8; n++) {
            const int col = 8 * n + 2 * t;
            *reinterpret_cast<float2*>(og + (size_t)g * 128 + col) =
                make_float2(C2[n][0], C2[n][1]);
            *reinterpret_cast<float2*>(og + (size_t)(g + 8) * 128 + col) =
                make_float2(C2[n][2], C2[n][3]);
        }
    }
}

} // anonymous namespace

extern "C" void kernel_launch(void* const* d_in, const int* in_sizes, int n_in,
                              void* d_out, int out_size) {
    const float* q = (const float*)d_in[0];
    const float* k = (const float*)d_in[1];
    const float* v = (const float*)d_in[2];
    float* out = (float*)d_out;

    cudaFuncSetAttribute(axial_attn_kernel,
                         cudaFuncAttributeMaxDynamicSharedMemorySize, SMEM_TOTAL);
    axial_attn_kernel<<<GRID, THREADS, SMEM_TOTAL>>>(q, k, v, out);
}

// round 13
// speedup vs baseline: 1.1120x; 1.0346x over previous
#include <cuda_runtime.h>
#include <cuda_fp16.h>
#include <cstdint>

#define DEVINL __device__ __forceinline__

namespace {

constexpr int BATCH = 32;
constexpr int LSEQ  = 8192;
constexpr int THREADS = 512;                 // 4 groups x 4 warps
constexpr int GRID = 152;                    // 1 CTA per SM
constexpr int TILES_PER_BATCH = 128;         // 64-row tiles

// ---- SMEM layout (bytes) ----
constexpr int SM_KSUM = 0;                   // 128 floats
constexpr int SM_XCH  = 512;                 // 4 groups x 128 float2 = 4096
constexpr int SM_PB   = 4608;                // 4 groups x 16384 (64x128 fp16, swz)
constexpr int SM_KH   = 70144;               // 128x128 fp16, XOR-swizzled (k-permuted rows)
constexpr int SM_KL   = SM_KH + 32768;
constexpr int SM_VH   = SM_KL + 32768;
constexpr int SMEM_TOTAL = SM_VH + 32768;    // 168448 B (1 CTA/SM)

// byte offset of fp16 element (r, c) in a tile with 256B rows; XOR swizzle
DEVINL uint32_t swz(int r, int c) {
    return (uint32_t)((r << 8) | ((((c >> 3) ^ (r & 7)) << 4) | ((c & 7) << 1)));
}

// contraction-dim permutation (see R8): orig o = 4t+2b+d -> pos 8b+2t+d per 16-block
DEVINL int kperm(int r) {
    int o = r & 15;
    return (r & 112) | ((o & 2) << 2) | ((o & 12) >> 1) | (o & 1);
}

DEVINL uint32_t smem_u32(const void* p) {
    uint32_t a;
    asm("{ .reg .u64 t; cvta.to.shared.u64 t, %1; cvt.u32.u64 %0, t; }" : "=r"(a) : "l"(p));
    return a;
}

DEVINL uint32_t packh(__half a, __half b) {
    return (uint32_t)__half_as_ushort(a) | ((uint32_t)__half_as_ushort(b) << 16);
}

DEVINL void split_pack2h(float a, float b, uint32_t& h, uint32_t& l) {
    __half ha = __float2half_rn(a), hb = __float2half_rn(b);
    __half la = __float2half_rn(a - __half2float(ha));
    __half lb = __float2half_rn(b - __half2float(hb));
    h = packh(ha, hb);
    l = packh(la, lb);
}
DEVINL uint32_t pack_hi2(float a, float b) {
    return packh(__float2half_rn(a), __float2half_rn(b));
}
DEVINL uint32_t hmul2u(uint32_t a, uint32_t b) {
    __half2 ha = *reinterpret_cast<__half2*>(&a);
    __half2 hb = *reinterpret_cast<__half2*>(&b);
    __half2 hr = __hmul2(ha, hb);
    return *reinterpret_cast<uint32_t*>(&hr);
}

// ldmatrix x4 address into a 256B-row swizzled tile
DEVINL uint32_t ldsm_addr(uint32_t tbase, int rbase, int c8base, int lane) {
    int ln = lane & 7, sel = lane >> 3;
    int r  = rbase + ln + ((sel & 1) << 3);
    int c8 = c8base + (sel >> 1);
    return tbase + swz(r, c8 << 3);
}

DEVINL void ldsm4(uint32_t a[4], uint32_t addr) {
    asm volatile("ldmatrix.sync.aligned.m8n8.x4.shared.b16 {%0,%1,%2,%3}, [%4];"
                 : "=r"(a[0]), "=r"(a[1]), "=r"(a[2]), "=r"(a[3]) : "r"(addr));
}
DEVINL void ldsm4t(uint32_t a[4], uint32_t addr) {
    asm volatile("ldmatrix.sync.aligned.m8n8.x4.trans.shared.b16 {%0,%1,%2,%3}, [%4];"
                 : "=r"(a[0]), "=r"(a[1]), "=r"(a[2]), "=r"(a[3]) : "r"(addr));
}

DEVINL void mma_fp16(float c[4], const uint32_t a[4], uint32_t b0, uint32_t b1) {
    asm volatile(
        "mma.sync.aligned.m16n8k16.row.col.f32.f16.f16.f32 "
        "{%0,%1,%2,%3}, {%4,%5,%6,%7}, {%8,%9}, {%0,%1,%2,%3};"
        : "+f"(c[0]), "+f"(c[1]), "+f"(c[2]), "+f"(c[3])
        : "r"(a[0]), "r"(a[1]), "r"(a[2]), "r"(a[3]), "r"(b0), "r"(b1));
}

DEVINL void barg(int id) {
    asm volatile("bar.sync %0, 128;" :: "r"(id) : "memory");
}

__global__ void __launch_bounds__(THREADS, 1)
axial_attn_kernel(const float* __restrict__ q, const float* __restrict__ k,
                  const float* __restrict__ v, float* __restrict__ out) {
    extern __shared__ char smem[];
    const uint32_t sb = smem_u32(smem);
    const int tid  = threadIdx.x;
    const int lane = tid & 31, w = tid >> 5;
    const int grp  = w >> 2;       // independent tile-stream group (0..3)
    const int wq   = w & 3;
    const int wr   = wq >> 1;      // 32-row block within 64-row tile
    const int sgrp = wq & 1;       // S-half (GEMM1) / d-half (GEMM2)
    const int g = lane >> 2, t = lane & 3;

    // ---- CTA -> (batch, tile chunk). 152 = 24*5 + 8*4 ----
    int bx = blockIdx.x;
    int batch, cidx, ncta;
    if (bx < 120) { batch = bx / 5; cidx = bx - batch * 5; ncta = 5; }
    else { int r = bx - 120; int bb = r >> 2; batch = 24 + bb; cidx = r & 3; ncta = 4; }
    const int base = TILES_PER_BATCH / ncta, rem = TILES_PER_BATCH - base * ncta;
    int tstart, tcnt;
    if (cidx < rem) { tcnt = base + 1; tstart = cidx * tcnt; }
    else            { tcnt = base;     tstart = rem * (base + 1) + (cidx - rem) * base; }

    float*  ksum = reinterpret_cast<float*>(smem + SM_KSUM);
    float2* xch  = reinterpret_cast<float2*>(smem + SM_XCH) + grp * 128;
    const int pbo = SM_PB + grp * 16384;
    const uint32_t pb = sb + pbo;

    const float* kb = k + (size_t)batch * (128 * 128);
    const float* vb = v + (size_t)batch * (128 * 128);

    // ======== one-time fill: K (hi/lo, permuted contraction rows, + row sums), V (hi) ========
    {
        const float4* kb4 = reinterpret_cast<const float4*>(kb);
        #pragma unroll 4
        for (int it = 0; it < 8; it++) {
            int e4  = it * THREADS + tid;          // warp covers exactly one row
            int row = e4 >> 5;
            int col = (e4 & 31) << 2;
            float4 tk = kb4[e4];
            uint32_t h01, l01, h23, l23;
            split_pack2h(tk.x, tk.y, h01, l01);
            split_pack2h(tk.z, tk.w, h23, l23);
            uint32_t off = swz(kperm(row), col);
            *reinterpret_cast<uint2*>(smem + SM_KH + off) = make_uint2(h01, h23);
            *reinterpret_cast<uint2*>(smem + SM_KL + off) = make_uint2(l01, l23);
            float s = (tk.x + tk.y) + (tk.z + tk.w);
            s += __shfl_xor_sync(0xffffffffu, s, 16);
            s += __shfl_xor_sync(0xffffffffu, s, 8);
            s += __shfl_xor_sync(0xffffffffu, s, 4);
            s += __shfl_xor_sync(0xffffffffu, s, 2);
            s += __shfl_xor_sync(0xffffffffu, s, 1);
            if (lane == 0) ksum[row] = s;
        }
        const float4* vb4 = reinterpret_cast<const float4*>(vb);
        #pragma unroll 4
        for (int it = 0; it < 8; it++) {
            int e4  = it * THREADS + tid;
            int row = e4 >> 5;
            int col = (e4 & 31) << 2;
            float4 tv = vb4[e4];
            uint32_t off = swz(row, col);
            *reinterpret_cast<uint2*>(smem + SM_VH + off) =
                make_uint2(pack_hi2(tv.x, tv.y), pack_hi2(tv.z, tv.w));
        }
    }
    __syncthreads();

    const int barid = 1 + grp;

    // ======== per-group tile loop (64-row tiles, groups interleave by 4) ========
    for (int ti = grp; ti < tcnt; ti += 4) {
        const int l0 = (tstart + ti) * 64;

        // warp's Q rows: l0 + 32*wr + {g, g+8, g+16... } (2 m-blocks of 16)
        const float* qrw = q + ((size_t)batch * LSEQ + l0 + 32 * wr + g) * 128 + 4 * t;

        // ---- GEMM1: 32 rows x 64 cols, kk-outer, Q loaded per-kk (transient) ----
        float C1[2][8][4];
        #pragma unroll
        for (int m = 0; m < 2; m++)
            #pragma unroll
            for (int jt = 0; jt < 8; jt++)
                #pragma unroll
                for (int i = 0; i < 4; i++) C1[m][jt][i] = 0.f;

        float qs00 = 0.f, qs01 = 0.f, qs10 = 0.f, qs11 = 0.f;

        #pragma unroll
        for (int kk = 0; kk < 8; kk++) {
            float4 qa = *reinterpret_cast<const float4*>(qrw + 16 * kk);              // m0 row g
            float4 qb = *reinterpret_cast<const float4*>(qrw + 8 * 128 + 16 * kk);    // m0 row g+8
            float4 qc = *reinterpret_cast<const float4*>(qrw + 16 * 128 + 16 * kk);   // m1 row g
            float4 qd = *reinterpret_cast<const float4*>(qrw + 24 * 128 + 16 * kk);   // m1 row g+8
            qs00 += (qa.x + qa.y) + (qa.z + qa.w);
            qs01 += (qb.x + qb.y) + (qb.z + qb.w);
            qs10 += (qc.x + qc.y) + (qc.z + qc.w);
            qs11 += (qd.x + qd.y) + (qd.z + qd.w);

            uint32_t A0h[4], A0l[4], A1h[4], A1l[4];
            split_pack2h(qa.x, qa.y, A0h[0], A0l[0]);
            split_pack2h(qb.x, qb.y, A0h[1], A0l[1]);
            split_pack2h(qa.z, qa.w, A0h[2], A0l[2]);
            split_pack2h(qb.z, qb.w, A0h[3], A0l[3]);
            split_pack2h(qc.x, qc.y, A1h[0], A1l[0]);
            split_pack2h(qd.x, qd.y, A1h[1], A1l[1]);
            split_pack2h(qc.z, qc.w, A1h[2], A1l[2]);
            split_pack2h(qd.z, qd.w, A1h[3], A1l[3]);

            #pragma unroll
            for (int jp = 0; jp < 4; jp++) {
                const int c8 = 8 * sgrp + 2 * jp;
                uint32_t bh[4], bl[4];
                ldsm4t(bh, ldsm_addr(sb + SM_KH, 16 * kk, c8, lane));
                ldsm4t(bl, ldsm_addr(sb + SM_KL, 16 * kk, c8, lane));
                // m-block 0
                mma_fp16(C1[0][2 * jp],     A0h, bh[0], bh[1]);
                mma_fp16(C1[0][2 * jp + 1], A0h, bh[2], bh[3]);
                mma_fp16(C1[0][2 * jp],     A0h, bl[0], bl[1]);
                mma_fp16(C1[0][2 * jp + 1], A0h, bl[2], bl[3]);
                mma_fp16(C1[0][2 * jp],     A0l, bh[0], bh[1]);
                mma_fp16(C1[0][2 * jp + 1], A0l, bh[2], bh[3]);
                // m-block 1 (same B fragments — the whole point)
                mma_fp16(C1[1][2 * jp],     A1h, bh[0], bh[1]);
                mma_fp16(C1[1][2 * jp + 1], A1h, bh[2], bh[3]);
                mma_fp16(C1[1][2 * jp],     A1h, bl[0], bl[1]);
                mma_fp16(C1[1][2 * jp + 1], A1h, bl[2], bl[3]);
                mma_fp16(C1[1][2 * jp],     A1l, bh[0], bh[1]);
                mma_fp16(C1[1][2 * jp + 1], A1l, bh[2], bh[3]);
            }
        }
        qs00 += __shfl_xor_sync(0xffffffffu, qs00, 1);
        qs00 += __shfl_xor_sync(0xffffffffu, qs00, 2);
        qs01 += __shfl_xor_sync(0xffffffffu, qs01, 1);
        qs01 += __shfl_xor_sync(0xffffffffu, qs01, 2);
        qs10 += __shfl_xor_sync(0xffffffffu, qs10, 1);
        qs10 += __shfl_xor_sync(0xffffffffu, qs10, 2);
        qs11 += __shfl_xor_sync(0xffffffffu, qs11, 1);
        qs11 += __shfl_xor_sync(0xffffffffu, qs11, 2);

        // ---- exact rank-1 term (ksum from SMEM) ----
        #pragma unroll
        for (int jt = 0; jt < 8; jt++) {
            float2 ks2 = *reinterpret_cast<const float2*>(ksum + 64 * sgrp + 8 * jt + 2 * t);
            C1[0][jt][0] += qs00 * ks2.x;
            C1[0][jt][1] += qs00 * ks2.y;
            C1[0][jt][2] += qs01 * ks2.x;
            C1[0][jt][3] += qs01 * ks2.y;
            C1[1][jt][0] += qs10 * ks2.x;
            C1[1][jt][1] += qs10 * ks2.y;
            C1[1][jt][2] += qs11 * ks2.x;
            C1[1][jt][3] += qs11 * ks2.y;
        }

        // ---- local softmax stats + exp (unscaled) ----
        float ml[2], mh[2], sl[2], sh[2];
        #pragma unroll
        for (int m = 0; m < 2; m++) {
            float a = -3.4e38f, b = -3.4e38f;
            #pragma unroll
            for (int jt = 0; jt < 8; jt++) {
                a = fmaxf(a, fmaxf(C1[m][jt][0], C1[m][jt][1]));
                b = fmaxf(b, fmaxf(C1[m][jt][2], C1[m][jt][3]));
            }
            a = fmaxf(a, __shfl_xor_sync(0xffffffffu, a, 1));
            a = fmaxf(a, __shfl_xor_sync(0xffffffffu, a, 2));
            b = fmaxf(b, __shfl_xor_sync(0xffffffffu, b, 1));
            b = fmaxf(b, __shfl_xor_sync(0xffffffffu, b, 2));
            float sa = 0.f, sbv = 0.f;
            #pragma unroll
            for (int jt = 0; jt < 8; jt++) {
                C1[m][jt][0] = __expf(C1[m][jt][0] - a);
                C1[m][jt][1] = __expf(C1[m][jt][1] - a);
                C1[m][jt][2] = __expf(C1[m][jt][2] - b);
                C1[m][jt][3] = __expf(C1[m][jt][3] - b);
                sa  += C1[m][jt][0] + C1[m][jt][1];
                sbv += C1[m][jt][2] + C1[m][jt][3];
            }
            sa  += __shfl_xor_sync(0xffffffffu, sa, 1);
            sa  += __shfl_xor_sync(0xffffffffu, sa, 2);
            sbv += __shfl_xor_sync(0xffffffffu, sbv, 1);
            sbv += __shfl_xor_sync(0xffffffffu, sbv, 2);
            ml[m] = a; mh[m] = b; sl[m] = sa; sh[m] = sbv;
        }

        // publish stats + write unscaled P (full buffer, both halves) — one barrier
        if (t == 0) {
            #pragma unroll
            for (int m = 0; m < 2; m++) {
                xch[sgrp * 64 + 32 * wr + 16 * m + g]     = make_float2(ml[m], sl[m]);
                xch[sgrp * 64 + 32 * wr + 16 * m + g + 8] = make_float2(mh[m], sh[m]);
            }
        }
        #pragma unroll
        for (int m = 0; m < 2; m++) {
            #pragma unroll
            for (int jt = 0; jt < 8; jt++) {
                const int col = 64 * sgrp + 8 * jt + 2 * t;
                *reinterpret_cast<uint32_t*>(smem + pbo + swz(32 * wr + 16 * m + g,     col)) =
                    pack_hi2(C1[m][jt][0], C1[m][jt][1]);
                *reinterpret_cast<uint32_t*>(smem + pbo + swz(32 * wr + 16 * m + g + 8, col)) =
                    pack_hi2(C1[m][jt][2], C1[m][jt][3]);
            }
        }
        barg(barid);   // stats + full P visible

        // ---- global scales: per (S-half, m-block, row-half) fp16 factors ----
        uint32_t FP[2][2][2];   // [S-half][m][rowhalf]
        #pragma unroll
        for (int m = 0; m < 2; m++) {
            float2 o_g  = xch[(1 - sgrp) * 64 + 32 * wr + 16 * m + g];
            float2 o_g8 = xch[(1 - sgrp) * 64 + 32 * wr + 16 * m + g + 8];
            float Mg  = fmaxf(ml[m], o_g.x);
            float Mg8 = fmaxf(mh[m], o_g8.x);
            float scg  = __expf(ml[m] - Mg),   spg  = __expf(o_g.x - Mg);
            float scg8 = __expf(mh[m] - Mg8),  spg8 = __expf(o_g8.x - Mg8);
            float invg  = 1.0f / (sl[m] * scg  + o_g.y  * spg);
            float invg8 = 1.0f / (sh[m] * scg8 + o_g8.y * spg8);
            float fog  = scg * invg,   fpg  = spg * invg;
            float fog8 = scg8 * invg8, fpg8 = spg8 * invg8;
            FP[sgrp][m][0]     = pack_hi2(fog, fog);
            FP[sgrp][m][1]     = pack_hi2(fog8, fog8);
            FP[1 - sgrp][m][0] = pack_hi2(fpg, fpg);
            FP[1 - sgrp][m][1] = pack_hi2(fpg8, fpg8);
        }

        // ---- GEMM2: O(32 rows x 64 d-cols) = P @ Vh, full S, A2 transient ----
        float C2[2][8][4];
        #pragma unroll
        for (int m = 0; m < 2; m++)
            #pragma unroll
            for (int jt = 0; jt < 8; jt++)
                #pragma unroll
                for (int i = 0; i < 4; i++) C2[m][jt][i] = 0.f;

        #pragma unroll
        for (int kk = 0; kk < 8; kk++) {
            const int hS = kk >> 2;
            uint32_t A2m[2][4];
            #pragma unroll
            for (int m = 0; m < 2; m++) {
                ldsm4(A2m[m], ldsm_addr(pb, 32 * wr + 16 * m, 2 * kk, lane));
                A2m[m][0] = hmul2u(A2m[m][0], FP[hS][m][0]);
                A2m[m][1] = hmul2u(A2m[m][1], FP[hS][m][1]);
                A2m[m][2] = hmul2u(A2m[m][2], FP[hS][m][0]);
                A2m[m][3] = hmul2u(A2m[m][3], FP[hS][m][1]);
            }
            #pragma unroll
            for (int jp = 0; jp < 4; jp++) {
                const int c8 = 8 * sgrp + 2 * jp;
                uint32_t bh[4];
                ldsm4t(bh, ldsm_addr(sb + SM_VH, 16 * kk, c8, lane));
                mma_fp16(C2[0][2 * jp],     A2m[0], bh[0], bh[1]);
                mma_fp16(C2[0][2 * jp + 1], A2m[0], bh[2], bh[3]);
                mma_fp16(C2[1][2 * jp],     A2m[1], bh[0], bh[1]);
                mma_fp16(C2[1][2 * jp + 1], A2m[1], bh[2], bh[3]);
            }
        }
        barg(barid);   // all P reads done; buffer free for next tile

        // ---- store (normalization folded into A2) ----
        #pragma unroll
        for (int m = 0; m < 2; m++) {
            float* og = out + ((size_t)batch * LSEQ + l0 + 32 * wr + 16 * m) * 128 + 64 * sgrp;
            #pragma unroll
            for (int jt = 0; jt < 8; jt++) {
                const int col = 8 * jt + 2 * t;
                *reinterpret_cast<float2*>(og + (size_t)g * 128 + col) =
                    make_float2(C2[m][jt][0], C2[m][jt][1]);
                *reinterpret_cast<float2*>(og + (size_t)(g + 8) * 128 + col) =
                    make_float2(C2[m][jt][2], C2[m][jt][3]);
            }
        }
    }
}

} // anonymous namespace

extern "C" void kernel_launch(void* const* d_in, const int* in_sizes, int n_in,
                              void* d_out, int out_size) {
    const float* q = (const float*)d_in[0];
    const float* k = (const float*)d_in[1];
    const float* v = (const float*)d_in[2];
    float* out = (float*)d_out;

    cudaFuncSetAttribute(axial_attn_kernel,
                         cudaFuncAttributeMaxDynamicSharedMemorySize, SMEM_TOTAL);
    axial_attn_kernel<<<GRID, THREADS, SMEM_TOTAL>>>(q, k, v, out);
}

// round 15
// speedup vs baseline: 1.4099x; 1.2679x over previous
#include <cuda_runtime.h>
#include <cuda_fp16.h>
#include <cstdint>

#define DEVINL __device__ __forceinline__

namespace {

constexpr int BATCH = 32;
constexpr int LSEQ  = 8192;
constexpr int THREADS = 512;                 // 16 independent warps
constexpr int GRID = 152;                    // 1 CTA per SM
constexpr int STRIPS_PER_BATCH = LSEQ / 16;  // 512 16-row strips
constexpr float LOG2E = 1.4426950408889634f;

// ---- SMEM layout (bytes) ----
constexpr int SM_KSUM = 0;                   // 128 floats
constexpr int SM_KH   = 1024;                // 128x128 fp16, XOR-swizzled (k-permuted rows)
constexpr int SM_KL   = SM_KH + 32768;
constexpr int SM_VH   = SM_KL + 32768;
constexpr int SMEM_TOTAL = SM_VH + 32768;    // 99328 B

// byte offset of fp16 element (r, c) in a tile with 256B rows; XOR swizzle
DEVINL uint32_t swz(int r, int c) {
    return (uint32_t)((r << 8) | ((((c >> 3) ^ (r & 7)) << 4) | ((c & 7) << 1)));
}

// contraction-dim permutation (see R8): orig o = 4t+2b+d -> pos 8b+2t+d per 16-block
DEVINL int kperm(int r) {
    int o = r & 15;
    return (r & 112) | ((o & 2) << 2) | ((o & 12) >> 1) | (o & 1);
}

DEVINL uint32_t smem_u32(const void* p) {
    uint32_t a;
    asm("{ .reg .u64 t; cvta.to.shared.u64 t, %1; cvt.u32.u64 %0, t; }" : "=r"(a) : "l"(p));
    return a;
}

DEVINL uint32_t packh(__half a, __half b) {
    return (uint32_t)__half_as_ushort(a) | ((uint32_t)__half_as_ushort(b) << 16);
}

DEVINL void split_pack2h(float a, float b, uint32_t& h, uint32_t& l) {
    __half ha = __float2half_rn(a), hb = __float2half_rn(b);
    __half la = __float2half_rn(a - __half2float(ha));
    __half lb = __float2half_rn(b - __half2float(hb));
    h = packh(ha, hb);
    l = packh(la, lb);
}
DEVINL uint32_t pack_hi2(float a, float b) {
    return packh(__float2half_rn(a), __float2half_rn(b));
}
DEVINL float ex2f(float x) {
    float r;
    asm("ex2.approx.ftz.f32 %0, %1;" : "=f"(r) : "f"(x));
    return r;
}

// ldmatrix x4 address into a 256B-row swizzled tile
DEVINL uint32_t ldsm_addr(uint32_t tbase, int rbase, int c8base, int lane) {
    int ln = lane & 7, sel = lane >> 3;
    int r  = rbase + ln + ((sel & 1) << 3);
    int c8 = c8base + (sel >> 1);
    return tbase + swz(r, c8 << 3);
}

DEVINL void ldsm4t(uint32_t a[4], uint32_t addr) {
    asm volatile("ldmatrix.sync.aligned.m8n8.x4.trans.shared.b16 {%0,%1,%2,%3}, [%4];"
                 : "=r"(a[0]), "=r"(a[1]), "=r"(a[2]), "=r"(a[3]) : "r"(addr));
}

DEVINL void mma_fp16(float c[4], const uint32_t a[4], uint32_t b0, uint32_t b1) {
    asm volatile(
        "mma.sync.aligned.m16n8k16.row.col.f32.f16.f16.f32 "
        "{%0,%1,%2,%3}, {%4,%5,%6,%7}, {%8,%9}, {%0,%1,%2,%3};"
        : "+f"(c[0]), "+f"(c[1]), "+f"(c[2]), "+f"(c[3])
        : "r"(a[0]), "r"(a[1]), "r"(a[2]), "r"(a[3]), "r"(b0), "r"(b1));
}

DEVINL void l2_prefetch(const void* p) {
    asm volatile("prefetch.global.L2 [%0];" :: "l"(p));
}

__global__ void __launch_bounds__(THREADS, 1)
axial_attn_kernel(const float* __restrict__ q, const float* __restrict__ k,
                  const float* __restrict__ v, float* __restrict__ out) {
    extern __shared__ char smem[];
    const uint32_t sb = smem_u32(smem);
    const int tid  = threadIdx.x;
    const int lane = tid & 31, w = tid >> 5;
    const int g = lane >> 2, t = lane & 3;

    // ---- CTA -> (batch, strip chunk). 152 = 24*5 + 8*4 ----
    int bx = blockIdx.x;
    int batch, cidx, ncta;
    if (bx < 120) { batch = bx / 5; cidx = bx - batch * 5; ncta = 5; }
    else { int r = bx - 120; int bb = r >> 2; batch = 24 + bb; cidx = r & 3; ncta = 4; }
    const int base = STRIPS_PER_BATCH / ncta, rem = STRIPS_PER_BATCH - base * ncta;
    int sstart, scnt;
    if (cidx < rem) { scnt = base + 1; sstart = cidx * scnt; }
    else            { scnt = base;     sstart = rem * (base + 1) + (cidx - rem) * base; }

    float* ksum = reinterpret_cast<float*>(smem + SM_KSUM);

    const float* kb = k + (size_t)batch * (128 * 128);
    const float* vb = v + (size_t)batch * (128 * 128);

    // ======== one-time fill: K (hi/lo, permuted contraction rows, + row sums), V (hi) ========
    {
        const float4* kb4 = reinterpret_cast<const float4*>(kb);
        #pragma unroll 4
        for (int it = 0; it < 8; it++) {
            int e4  = it * THREADS + tid;          // warp covers exactly one row
            int row = e4 >> 5;
            int col = (e4 & 31) << 2;
            float4 tk = kb4[e4];
            uint32_t h01, l01, h23, l23;
            split_pack2h(tk.x, tk.y, h01, l01);
            split_pack2h(tk.z, tk.w, h23, l23);
            uint32_t off = swz(kperm(row), col);
            *reinterpret_cast<uint2*>(smem + SM_KH + off) = make_uint2(h01, h23);
            *reinterpret_cast<uint2*>(smem + SM_KL + off) = make_uint2(l01, l23);
            float s = (tk.x + tk.y) + (tk.z + tk.w);
            s += __shfl_xor_sync(0xffffffffu, s, 16);
            s += __shfl_xor_sync(0xffffffffu, s, 8);
            s += __shfl_xor_sync(0xffffffffu, s, 4);
            s += __shfl_xor_sync(0xffffffffu, s, 2);
            s += __shfl_xor_sync(0xffffffffu, s, 1);
            if (lane == 0) ksum[row] = s;
        }
        const float4* vb4 = reinterpret_cast<const float4*>(vb);
        #pragma unroll 4
        for (int it = 0; it < 8; it++) {
            int e4  = it * THREADS + tid;
            int row = e4 >> 5;
            int col = (e4 & 31) << 2;
            float4 tv = vb4[e4];
            uint32_t off = swz(row, col);
            *reinterpret_cast<uint2*>(smem + SM_VH + off) =
                make_uint2(pack_hi2(tv.x, tv.y), pack_hi2(tv.z, tv.w));
        }
    }
    __syncthreads();

    // ======== per-warp strip loop (16 rows x full 128 cols; no barriers) ========
    for (int s = w; s < scnt; s += 16) {
        const int r0 = (sstart + s) * 16;
        const float* qrw = q + ((size_t)batch * LSEQ + r0 + g) * 128 + 4 * t;

        // ---- GEMM1: S2 = log2e * (Q @ K), kk-outer, Q transient ----
        float C1[16][4];
        #pragma unroll
        for (int jt = 0; jt < 16; jt++)
            #pragma unroll
            for (int i = 0; i < 4; i++) C1[jt][i] = 0.f;

        float qs0 = 0.f, qs1 = 0.f;
        #pragma unroll
        for (int kk = 0; kk < 8; kk++) {
            float4 qa = *reinterpret_cast<const float4*>(qrw + 16 * kk);            // row g
            float4 qb = *reinterpret_cast<const float4*>(qrw + 8 * 128 + 16 * kk);  // row g+8
            qs0 += (qa.x + qa.y) + (qa.z + qa.w);
            qs1 += (qb.x + qb.y) + (qb.z + qb.w);
            // scale by log2e before the split: MMA computes (log2e*Q)*K
            qa.x *= LOG2E; qa.y *= LOG2E; qa.z *= LOG2E; qa.w *= LOG2E;
            qb.x *= LOG2E; qb.y *= LOG2E; qb.z *= LOG2E; qb.w *= LOG2E;
            uint32_t Ah[4], Al[4];
            split_pack2h(qa.x, qa.y, Ah[0], Al[0]);
            split_pack2h(qb.x, qb.y, Ah[1], Al[1]);
            split_pack2h(qa.z, qa.w, Ah[2], Al[2]);
            split_pack2h(qb.z, qb.w, Ah[3], Al[3]);
            #pragma unroll
            for (int jp = 0; jp < 8; jp++) {
                uint32_t bh[4], bl[4];
                ldsm4t(bh, ldsm_addr(sb + SM_KH, 16 * kk, 2 * jp, lane));
                ldsm4t(bl, ldsm_addr(sb + SM_KL, 16 * kk, 2 * jp, lane));
                mma_fp16(C1[2 * jp],     Ah, bh[0], bh[1]);
                mma_fp16(C1[2 * jp + 1], Ah, bh[2], bh[3]);
                mma_fp16(C1[2 * jp],     Ah, bl[0], bl[1]);
                mma_fp16(C1[2 * jp + 1], Ah, bl[2], bl[3]);
                mma_fp16(C1[2 * jp],     Al, bh[0], bh[1]);
                mma_fp16(C1[2 * jp + 1], Al, bh[2], bh[3]);
            }
        }
        qs0 += __shfl_xor_sync(0xffffffffu, qs0, 1);
        qs0 += __shfl_xor_sync(0xffffffffu, qs0, 2);
        qs1 += __shfl_xor_sync(0xffffffffu, qs1, 1);
        qs1 += __shfl_xor_sync(0xffffffffu, qs1, 2);
        qs0 *= LOG2E;   // rank-1 term also in base-2 domain
        qs1 *= LOG2E;

        // ---- exact rank-1 term: += (log2e*qsum[row]) * ksum[col] ----
        #pragma unroll
        for (int jt = 0; jt < 16; jt++) {
            float2 ks2 = *reinterpret_cast<const float2*>(ksum + 8 * jt + 2 * t);
            C1[jt][0] += qs0 * ks2.x;
            C1[jt][1] += qs0 * ks2.y;
            C1[jt][2] += qs1 * ks2.x;
            C1[jt][3] += qs1 * ks2.y;
        }

        // ---- in-warp softmax (base 2): rows g and g+8, quad-reduced ----
        float m0 = -3.4e38f, m1 = -3.4e38f;
        #pragma unroll
        for (int jt = 0; jt < 16; jt++) {
            m0 = fmaxf(m0, fmaxf(C1[jt][0], C1[jt][1]));
            m1 = fmaxf(m1, fmaxf(C1[jt][2], C1[jt][3]));
        }
        m0 = fmaxf(m0, __shfl_xor_sync(0xffffffffu, m0, 1));
        m0 = fmaxf(m0, __shfl_xor_sync(0xffffffffu, m0, 2));
        m1 = fmaxf(m1, __shfl_xor_sync(0xffffffffu, m1, 1));
        m1 = fmaxf(m1, __shfl_xor_sync(0xffffffffu, m1, 2));

        float s0 = 0.f, s1 = 0.f;
        #pragma unroll
        for (int jt = 0; jt < 16; jt++) {
            C1[jt][0] = ex2f(C1[jt][0] - m0);
            C1[jt][1] = ex2f(C1[jt][1] - m0);
            C1[jt][2] = ex2f(C1[jt][2] - m1);
            C1[jt][3] = ex2f(C1[jt][3] - m1);
            s0 += C1[jt][0] + C1[jt][1];
            s1 += C1[jt][2] + C1[jt][3];
        }
        s0 += __shfl_xor_sync(0xffffffffu, s0, 1);
        s0 += __shfl_xor_sync(0xffffffffu, s0, 2);
        s1 += __shfl_xor_sync(0xffffffffu, s1, 1);
        s1 += __shfl_xor_sync(0xffffffffu, s1, 2);
        const float inv0 = 1.0f / s0;
        const float inv1 = 1.0f / s1;

        // ---- P: C-frag -> A-frag in registers, normalization folded (single fp16 round) ----
        uint32_t A2[8][4];
        #pragma unroll
        for (int kk = 0; kk < 8; kk++) {
            A2[kk][0] = pack_hi2(C1[2 * kk][0] * inv0,     C1[2 * kk][1] * inv0);
            A2[kk][1] = pack_hi2(C1[2 * kk][2] * inv1,     C1[2 * kk][3] * inv1);
            A2[kk][2] = pack_hi2(C1[2 * kk + 1][0] * inv0, C1[2 * kk + 1][1] * inv0);
            A2[kk][3] = pack_hi2(C1[2 * kk + 1][2] * inv1, C1[2 * kk + 1][3] * inv1);
        }

        // ---- L2 prefetch next strip's Q rows ----
        if (s + 16 < scnt) {
            const float* pn = qrw + (size_t)256 * 128;   // 16 warps * 16 rows ahead
            #pragma unroll
            for (int kk = 0; kk < 8; kk += 2) {
                l2_prefetch(pn + 16 * kk);
                l2_prefetch(pn + 8 * 128 + 16 * kk);
            }
        }

        // ---- GEMM2: O(16 x 128) = P @ Vh, full S contraction ----
        float C2[16][4];
        #pragma unroll
        for (int jt = 0; jt < 16; jt++)
            #pragma unroll
            for (int i = 0; i < 4; i++) C2[jt][i] = 0.f;

        #pragma unroll
        for (int kk = 0; kk < 8; kk++) {
            #pragma unroll
            for (int jp = 0; jp < 8; jp++) {
                uint32_t bh[4];
                ldsm4t(bh, ldsm_addr(sb + SM_VH, 16 * kk, 2 * jp, lane));
                mma_fp16(C2[2 * jp],     A2[kk], bh[0], bh[1]);
                mma_fp16(C2[2 * jp + 1], A2[kk], bh[2], bh[3]);
            }
        }

        // ---- store ----
        float* og = out + ((size_t)batch * LSEQ + r0) * 128;
        #pragma unroll
        for (int jt = 0; jt < 16; jt++) {
            const int col = 8 * jt + 2 * t;
            *reinterpret_cast<float2*>(og + (size_t)g * 128 + col) =
                make_float2(C2[jt][0], C2[jt][1]);
            *reinterpret_cast<float2*>(og + (size_t)(g + 8) * 128 + col) =
                make_float2(C2[jt][2], C2[jt][3]);
        }
    }
}

} // anonymous namespace

extern "C" void kernel_launch(void* const* d_in, const int* in_sizes, int n_in,
                              void* d_out, int out_size) {
    const float* q = (const float*)d_in[0];
    const float* k = (const float*)d_in[1];
    const float* v = (const float*)d_in[2];
    float* out = (float*)d_out;

    cudaFuncSetAttribute(axial_attn_kernel,
                         cudaFuncAttributeMaxDynamicSharedMemorySize, SMEM_TOTAL);
    axial_attn_kernel<<<GRID, THREADS, SMEM_TOTAL>>>(q, k, v, out);
}